// round 13
// baseline (speedup 1.0000x reference)
#include <cuda_runtime.h>
#include <cuda_bf16.h>
#include <cfloat>
#include <math.h>
#include <stdint.h>

#define B_   1024
#define N_   50000
#define D_   256
#define MA_  200
#define K_   8
#define CAND 16
#define TILES 391              // ceil(50000/128)

// ---------- device scratch ----------
__device__ float g_qh[B_ * D_];                    // exact fp32 (rescaled)
__device__ float g_mh[(size_t)N_ * D_];
__device__ uint32_t g_qhb[B_ * D_ / 2];            // bf16 pairs for filter
__device__ uint32_t g_mhb[(size_t)N_ * D_ / 2];
__device__ float g_qsq[B_];
__device__ float g_msq[N_];
__device__ uint32_t g_cand[(size_t)B_ * TILES * 24];   // 38.4 MB

// ---------- helpers ----------
__device__ __forceinline__ unsigned long long pk2(float x, float y) {
    unsigned long long u;
    asm("mov.b64 %0, {%1,%2};" : "=l"(u) : "f"(x), "f"(y));
    return u;
}
__device__ __forceinline__ float2 up2(unsigned long long u) {
    float2 v;
    asm("mov.b64 {%0,%1}, %2;" : "=f"(v.x), "=f"(v.y) : "l"(u));
    return v;
}
__device__ __forceinline__ void fma2(unsigned long long& c, unsigned long long a,
                                     unsigned long long b) {
    asm("fma.rn.f32x2 %0, %1, %2, %3;" : "=l"(c) : "l"(a), "l"(b), "l"(c));
}
__device__ __forceinline__ uint32_t umin32(uint32_t a, uint32_t b) { return a < b ? a : b; }

// D += A(16x16 bf16, row) @ B(16x8 bf16, col), fp32 accum
__device__ __forceinline__ void mma_bf16(float* d, uint32_t a0, uint32_t a1,
                                         uint32_t a2, uint32_t a3,
                                         uint32_t b0, uint32_t b1) {
    asm volatile(
        "mma.sync.aligned.m16n8k16.row.col.f32.bf16.bf16.f32 "
        "{%0,%1,%2,%3}, {%4,%5,%6,%7}, {%8,%9}, {%0,%1,%2,%3};"
        : "+f"(d[0]), "+f"(d[1]), "+f"(d[2]), "+f"(d[3])
        : "r"(a0), "r"(a1), "r"(a2), "r"(a3), "r"(b0), "r"(b1));
}

// fp32 micro-kernel for transform (8q x 4c per thread), double-buffered smem
#define MICRO_KK(buf, kk)                                                     \
    {                                                                         \
        float4 q0 = *reinterpret_cast<const float4*>(&As[buf][(kk) * 64 + w8]);\
        float4 q1 = *reinterpret_cast<const float4*>(&As[buf][(kk) * 64 + w8 + 4]);\
        ulonglong2 b = *reinterpret_cast<const ulonglong2*>(&Bs[buf][(kk) * 128 + lane4]); \
        unsigned long long a0 = pk2(q0.x, q0.x), a1 = pk2(q0.y, q0.y);        \
        unsigned long long a2 = pk2(q0.z, q0.z), a3 = pk2(q0.w, q0.w);        \
        unsigned long long a4 = pk2(q1.x, q1.x), a5 = pk2(q1.y, q1.y);        \
        unsigned long long a6 = pk2(q1.z, q1.z), a7 = pk2(q1.w, q1.w);        \
        fma2(acc[0][0], a0, b.x); fma2(acc[0][1], a0, b.y);                   \
        fma2(acc[1][0], a1, b.x); fma2(acc[1][1], a1, b.y);                   \
        fma2(acc[2][0], a2, b.x); fma2(acc[2][1], a2, b.y);                   \
        fma2(acc[3][0], a3, b.x); fma2(acc[3][1], a3, b.y);                   \
        fma2(acc[4][0], a4, b.x); fma2(acc[4][1], a4, b.y);                   \
        fma2(acc[5][0], a5, b.x); fma2(acc[5][1], a5, b.y);                   \
        fma2(acc[6][0], a6, b.x); fma2(acc[6][1], a6, b.y);                   \
        fma2(acc[7][0], a7, b.x); fma2(acc[7][1], a7, b.y);                   \
    }

// ================= kernel 1: h = tanh(X @ W + b)  (fp32, pipelined) =================
__global__ void __launch_bounds__(256, 2) k_transform(const float* __restrict__ A,
                                                      const float* __restrict__ W,
                                                      const float* __restrict__ bias,
                                                      int M, int to_mem) {
    __shared__ __align__(16) float As[2][32 * 64];    // 2 x 8 KB
    __shared__ __align__(16) float Bs[2][32 * 128];   // 2 x 16 KB
    float* __restrict__ out = to_mem ? g_mh : g_qh;

    const int tid = threadIdx.x;
    const int w8 = (tid >> 5) * 8;
    const int lane4 = (tid & 31) * 4;
    const int rbase = blockIdx.x * 64;
    const int cbase = blockIdx.y * 128;

    unsigned long long acc[8][2];
#pragma unroll
    for (int i = 0; i < 8; i++) { acc[i][0] = 0ull; acc[i][1] = 0ull; }

    const int sr = tid & 63;
    const int skq = tid >> 6;
    const int wkw = tid >> 3;
    const int wcs = (tid & 7) * 16;

    float4 av0, av1, wv0, wv1, wv2, wv3;    // staging registers

#define T_LDG(ko)                                                               \
    {                                                                           \
        int gr = rbase + sr;                                                    \
        av0 = make_float4(0,0,0,0); av1 = make_float4(0,0,0,0);                 \
        if (gr < M) {                                                           \
            const float4* p = reinterpret_cast<const float4*>(A + (size_t)gr * D_ + (ko) + skq * 8); \
            av0 = p[0]; av1 = p[1];                                             \
        }                                                                       \
        const float4* pw = reinterpret_cast<const float4*>(W + (size_t)((ko) + wkw) * D_ + cbase + wcs); \
        wv0 = pw[0]; wv1 = pw[1]; wv2 = pw[2]; wv3 = pw[3];                     \
    }
#define T_STS(buf)                                                              \
    {                                                                           \
        float vv[8] = {av0.x,av0.y,av0.z,av0.w,av1.x,av1.y,av1.z,av1.w};        \
        _Pragma("unroll")                                                       \
        for (int i = 0; i < 8; i++) As[buf][(skq * 8 + i) * 64 + sr] = vv[i];   \
        float4* qd = reinterpret_cast<float4*>(&Bs[buf][wkw * 128 + wcs]);      \
        qd[0] = wv0; qd[1] = wv1; qd[2] = wv2; qd[3] = wv3;                     \
    }

    T_LDG(0)
    T_STS(0)
    for (int ch = 0; ch < 8; ch++) {
        __syncthreads();
        if (ch < 7) T_LDG((ch + 1) * 32)
        const int buf = ch & 1;
#pragma unroll
        for (int kk = 0; kk < 32; kk++) MICRO_KK(buf, kk)
        if (ch < 7) T_STS((ch + 1) & 1)
    }

    const int c0 = cbase + lane4;
    float4 b4 = *reinterpret_cast<const float4*>(bias + c0);
#pragma unroll
    for (int i = 0; i < 8; i++) {
        int r = rbase + w8 + i;
        if (r < M) {
            float2 v0 = up2(acc[i][0]), v1 = up2(acc[i][1]);
            float4 o;
            o.x = tanhf(v0.x + b4.x); o.y = tanhf(v0.y + b4.y);
            o.z = tanhf(v1.x + b4.z); o.w = tanhf(v1.y + b4.w);
            *reinterpret_cast<float4*>(out + (size_t)r * D_ + c0) = o;
        }
    }
}

// ==== kernel 2: Poincare rescale (in place) + sumsq + bf16 pack ====
__global__ void __launch_bounds__(256) k_normalize(int which, int M) {
    float* __restrict__ h  = which ? g_mh  : g_qh;
    float* __restrict__ sq = which ? g_msq : g_qsq;
    uint32_t* __restrict__ hb = which ? g_mhb : g_qhb;
    int row = blockIdx.x * 8 + (threadIdx.x >> 5);
    if (row >= M) return;
    int lane = threadIdx.x & 31;
    size_t off = (size_t)row * D_ + lane * 8;
    float4* p = reinterpret_cast<float4*>(h + off);
    float4 v0 = p[0], v1 = p[1];
    float s = v0.x*v0.x + v0.y*v0.y + v0.z*v0.z + v0.w*v0.w
            + v1.x*v1.x + v1.y*v1.y + v1.z*v1.z + v1.w*v1.w;
#pragma unroll
    for (int o = 16; o; o >>= 1) s += __shfl_xor_sync(0xffffffffu, s, o);
    float norm = sqrtf(s);
    float scale = (norm > 0.95f) ? (0.95f / norm) : 1.0f;
    float y[8] = {v0.x*scale, v0.y*scale, v0.z*scale, v0.w*scale,
                  v1.x*scale, v1.y*scale, v1.z*scale, v1.w*scale};
    p[0] = make_float4(y[0], y[1], y[2], y[3]);
    p[1] = make_float4(y[4], y[5], y[6], y[7]);
    float s2 = 0.0f;
#pragma unroll
    for (int i = 0; i < 8; i++) s2 += y[i] * y[i];
#pragma unroll
    for (int o = 16; o; o >>= 1) s2 += __shfl_xor_sync(0xffffffffu, s2, o);
    if (lane == 0) sq[row] = s2;
    uint32_t wds[4];
#pragma unroll
    for (int i = 0; i < 4; i++) {
        __nv_bfloat162 bb = __floats2bfloat162_rn(y[2*i], y[2*i+1]);
        wds[i] = *reinterpret_cast<uint32_t*>(&bb);
    }
    *reinterpret_cast<uint4*>(hb + (size_t)row * 128 + lane * 4) =
        make_uint4(wds[0], wds[1], wds[2], wds[3]);
}

// ==== kernel 3: bf16 filter GEMM + fused top-3 candidates (pipelined) ====
// block 64q x 128m; 8 warps = 4 qw x 2 nw; warp 16q x 64m; mma m16n8k16.
// smem dword = (word w, word w+4) -> conflict-free LDS.64 fragments.
__global__ void __launch_bounds__(256, 2) k_dist_cand() {
    __shared__ __align__(16) uint2 Ap[2][4 * 64 * 4];     // 2 x 8 KB
    __shared__ __align__(16) uint2 Mp[2][4 * 128 * 4];    // 2 x 16 KB

    const int tid = threadIdx.x;
    const int warp = tid >> 5, lane = tid & 31;
    const int g = lane >> 2, tig = lane & 3;
    const int qw = (warp & 3) * 16;
    const int nwbit = warp >> 2;
    const int nw = nwbit * 64;
    const int qbase = blockIdx.x * 64;
    const int mb = blockIdx.y * 128;

    float acc[8][4];
#pragma unroll
    for (int j = 0; j < 8; j++)
#pragma unroll
        for (int c = 0; c < 4; c++) acc[j][c] = 0.0f;

    const int sq_ = tid & 63, sks = tid >> 6;
    const int mr0 = tid & 127, mk0 = tid >> 7;          // M staging iter 0
    const int mk1 = mk0 + 2;                             // M staging iter 1 (same row)

    uint4 qa_, qb_, m0a, m0b, m1a, m1b;                  // staging registers

#define D_LDG(ch)                                                               \
    {                                                                           \
        const int wb = (ch) * 32;                                               \
        const uint4* p = reinterpret_cast<const uint4*>(                        \
            g_qhb + (size_t)(qbase + sq_) * 128 + wb + sks * 8);                \
        qa_ = p[0]; qb_ = p[1];                                                 \
        int gm = mb + mr0;                                                      \
        m0a = make_uint4(0,0,0,0); m0b = make_uint4(0,0,0,0);                   \
        m1a = make_uint4(0,0,0,0); m1b = make_uint4(0,0,0,0);                   \
        if (gm < N_) {                                                          \
            const uint4* pm0 = reinterpret_cast<const uint4*>(                  \
                g_mhb + (size_t)gm * 128 + wb + mk0 * 8);                       \
            m0a = pm0[0]; m0b = pm0[1];                                         \
            const uint4* pm1 = reinterpret_cast<const uint4*>(                  \
                g_mhb + (size_t)gm * 128 + wb + mk1 * 8);                       \
            m1a = pm1[0]; m1b = pm1[1];                                         \
        }                                                                       \
    }
#define D_STS(buf)                                                              \
    {                                                                           \
        uint2* d = &Ap[buf][(sks * 64 + sq_) * 4];                              \
        d[0] = make_uint2(qa_.x, qb_.x);                                        \
        d[1] = make_uint2(qa_.y, qb_.y);                                        \
        d[2] = make_uint2(qa_.z, qb_.z);                                        \
        d[3] = make_uint2(qa_.w, qb_.w);                                        \
        uint2* d0 = &Mp[buf][(mk0 * 128 + mr0) * 4];                            \
        d0[0] = make_uint2(m0a.x, m0b.x);                                       \
        d0[1] = make_uint2(m0a.y, m0b.y);                                       \
        d0[2] = make_uint2(m0a.z, m0b.z);                                       \
        d0[3] = make_uint2(m0a.w, m0b.w);                                       \
        uint2* d1 = &Mp[buf][(mk1 * 128 + mr0) * 4];                            \
        d1[0] = make_uint2(m1a.x, m1b.x);                                       \
        d1[1] = make_uint2(m1a.y, m1b.y);                                       \
        d1[2] = make_uint2(m1a.z, m1b.z);                                       \
        d1[3] = make_uint2(m1a.w, m1b.w);                                       \
    }

    D_LDG(0)
    D_STS(0)
    for (int ch = 0; ch < 4; ch++) {
        __syncthreads();
        if (ch < 3) D_LDG(ch + 1)
        const int buf = ch & 1;
#pragma unroll
        for (int ks = 0; ks < 4; ks++) {
            uint2 aA = Ap[buf][(ks * 64 + qw + g) * 4 + tig];       // a0, a2
            uint2 aB = Ap[buf][(ks * 64 + qw + g + 8) * 4 + tig];   // a1, a3
#pragma unroll
            for (int jn = 0; jn < 8; jn++) {
                uint2 bb = Mp[buf][(ks * 128 + nw + jn * 8 + g) * 4 + tig];
                mma_bf16(acc[jn], aA.x, aB.x, aA.y, aB.y, bb.x, bb.y);
            }
        }
        if (ch < 3) D_STS((ch + 1) & 1)
    }

    // epilogue: approx arg + per-thread top-3 (32-bit keys), per q-row
    const int q0 = qbase + qw + g;
#pragma unroll
    for (int i = 0; i < 2; i++) {
        const int qr = q0 + i * 8;
        const float qs = g_qsq[qr];
        const float qa = 1.0f - qs;
        uint32_t t0 = 0xFFFFFFFFu, t1 = 0xFFFFFFFFu, t2 = 0xFFFFFFFFu;
#pragma unroll
        for (int jn = 0; jn < 8; jn++) {
#pragma unroll
            for (int h = 0; h < 2; h++) {
                int m = mb + nw + jn * 8 + 2 * tig + h;
                if (m < N_) {
                    float ms = g_msq[m];
                    float dot = acc[jn][i * 2 + h];
                    float diff = fmaxf(qs + ms - 2.0f * dot, 0.0f);
                    float arg = 1.0f + (2.0f * diff) / (qa * (1.0f - ms) + 1e-8f);
                    uint32_t key = (__float_as_uint(arg) & 0xFFFF0000u) | (uint32_t)m;
                    if (key < t2) {
                        if (key < t1) {
                            t2 = t1;
                            if (key < t0) { t1 = t0; t0 = key; } else t1 = key;
                        } else t2 = key;
                    }
                }
            }
        }
        size_t base = ((size_t)qr * TILES + blockIdx.y) * 24 + (nwbit * 4 + tig) * 3;
        g_cand[base]     = t0;
        g_cand[base + 1] = t1;
        g_cand[base + 2] = t2;
    }
}

// ==== kernel 4: merge candidates -> approx top-16 -> exact re-rank -> out ====
__global__ void __launch_bounds__(256) k_merge(const float* __restrict__ masks,
                                               float* __restrict__ out) {
    const int q = blockIdx.x, tid = threadIdx.x;
    const int wid = tid >> 5, lane = tid & 31;
    const uint32_t* __restrict__ cand = g_cand + (size_t)q * (TILES * 24);
    const int TOT = TILES * 24;

    uint32_t best[6];
#pragma unroll
    for (int s = 0; s < 6; s++) best[s] = 0xFFFFFFFFu;
    for (int i = tid; i < TOT; i += 256) {
        uint32_t k = cand[i];
        if (k < best[5]) {
            best[5] = k;
#pragma unroll
            for (int s = 5; s > 0; s--) {
                if (best[s] < best[s - 1]) {
                    uint32_t t = best[s]; best[s] = best[s - 1]; best[s - 1] = t;
                }
            }
        }
    }

    __shared__ uint32_t red[8];
    __shared__ uint32_t wks;
    __shared__ int cidx[CAND];
    __shared__ unsigned long long ekeys[CAND];
    __shared__ int fidx[K_];

    for (int s = 0; s < CAND; s++) {
        uint32_t lm = best[0];
#pragma unroll
        for (int o = 16; o; o >>= 1)
            lm = umin32(lm, __shfl_xor_sync(0xffffffffu, lm, o));
        if (lane == 0) red[wid] = lm;
        __syncthreads();
        if (tid == 0) {
            uint32_t m = red[0];
#pragma unroll
            for (int i = 1; i < 8; i++) m = umin32(m, red[i]);
            wks = m;
            cidx[s] = (int)(m & 0xFFFFu);
        }
        __syncthreads();
        if (best[0] == wks) {
#pragma unroll
            for (int i = 0; i < 5; i++) best[i] = best[i + 1];
            best[5] = 0xFFFFFFFFu;
        }
        __syncthreads();
    }

    // exact fp32 re-rank of 16 candidates (one per warp, 2 rounds)
    const float4* qp = reinterpret_cast<const float4*>(g_qh + (size_t)q * D_ + lane * 8);
    float4 a0 = qp[0], a1 = qp[1];
    const float qs = g_qsq[q];
    const float qa = 1.0f - qs;
#pragma unroll
    for (int r = 0; r < 2; r++) {
        int c = wid + 8 * r;
        int idx = cidx[c];
        const float4* mp = reinterpret_cast<const float4*>(g_mh + (size_t)idx * D_ + lane * 8);
        float4 b0 = mp[0], b1 = mp[1];
        float dot = a0.x*b0.x + a0.y*b0.y + a0.z*b0.z + a0.w*b0.w
                  + a1.x*b1.x + a1.y*b1.y + a1.z*b1.z + a1.w*b1.w;
#pragma unroll
        for (int o = 16; o; o >>= 1) dot += __shfl_xor_sync(0xffffffffu, dot, o);
        if (lane == 0) {
            float ms = g_msq[idx];
            float diff = fmaxf(qs + ms - 2.0f * dot, 0.0f);
            float arg = 1.0f + (2.0f * diff) / (qa * (1.0f - ms) + 1e-8f);
            ekeys[c] = ((unsigned long long)__float_as_uint(arg) << 32) | (unsigned)idx;
        }
    }
    __syncthreads();

    if (tid == 0) {
        unsigned long long k[CAND];
#pragma unroll
        for (int i = 0; i < CAND; i++) k[i] = ekeys[i];
#pragma unroll
        for (int i = 1; i < CAND; i++) {
            unsigned long long x = k[i];
            int j = i - 1;
            while (j >= 0 && k[j] > x) { k[j + 1] = k[j]; j--; }
            k[j + 1] = x;
        }
        float d[K_], w[K_], sum = 0.0f;
#pragma unroll
        for (int s = 0; s < K_; s++) {
            float arg = __uint_as_float((unsigned)(k[s] >> 32));
            d[s] = acoshf(fmaxf(arg, 1.0f + 1e-6f));
            fidx[s] = (int)(unsigned)(k[s] & 0xffffffffu);
        }
#pragma unroll
        for (int s = 0; s < K_; s++) { w[s] = expf(d[0] - d[s]); sum += w[s]; }
#pragma unroll
        for (int s = 0; s < K_; s++)
            out[(size_t)q * K_ + s] = w[s] / sum;
    }
    __syncthreads();

    float* __restrict__ hints = out + (size_t)B_ * K_;
    for (int s = 0; s < K_; s++) {
        const float* __restrict__ src = masks + (size_t)fidx[s] * MA_;
        float* __restrict__ dst = hints + ((size_t)q * K_ + s) * MA_;
        for (int t = tid; t < MA_; t += 256) dst[t] = src[t];
    }
}

extern "C" void kernel_launch(void* const* d_in, const int* in_sizes, int n_in,
                              void* d_out, int out_size) {
    const float* q_emb  = (const float*)d_in[0];
    const float* m_emb  = (const float*)d_in[1];
    const float* masks  = (const float*)d_in[2];
    const float* W      = (const float*)d_in[3];
    const float* b      = (const float*)d_in[4];
    float* out = (float*)d_out;

    k_transform<<<dim3(B_ / 64, 2), 256>>>(q_emb, W, b, B_, 0);
    k_transform<<<dim3((N_ + 63) / 64, 2), 256>>>(m_emb, W, b, N_, 1);
    k_normalize<<<(B_ + 7) / 8, 256>>>(0, B_);
    k_normalize<<<(N_ + 7) / 8, 256>>>(1, N_);
    k_dist_cand<<<dim3(B_ / 64, TILES), 256>>>();
    k_merge<<<B_, 256>>>(masks, out);
}

// round 14
// speedup vs baseline: 1.1822x; 1.1822x over previous
#include <cuda_runtime.h>
#include <cuda_bf16.h>
#include <cfloat>
#include <math.h>
#include <stdint.h>

#define B_   1024
#define N_   50000
#define D_   256
#define MA_  200
#define K_   8
#define CAND 32
#define TILES 391              // ceil(50000/128)

// ---------- device scratch ----------
__device__ float g_qh[B_ * D_];                    // exact fp32 (rescaled)
__device__ float g_mh[(size_t)N_ * D_];
__device__ uint32_t g_qhb[B_ * 64];                // int8 packed words (4 s8/word)
__device__ uint32_t g_mhb[(size_t)N_ * 64];
__device__ float g_qsq[B_];
__device__ float g_msq[N_];
__device__ uint32_t g_cand[(size_t)B_ * TILES * 24];   // 38.4 MB

#define Q_SCALE   133.684210f          // 127 / 0.95
#define DOT_SCALE 5.59450274e-5f       // (0.95/127)^2

// ---------- helpers ----------
__device__ __forceinline__ unsigned long long pk2(float x, float y) {
    unsigned long long u;
    asm("mov.b64 %0, {%1,%2};" : "=l"(u) : "f"(x), "f"(y));
    return u;
}
__device__ __forceinline__ float2 up2(unsigned long long u) {
    float2 v;
    asm("mov.b64 {%0,%1}, %2;" : "=f"(v.x), "=f"(v.y) : "l"(u));
    return v;
}
__device__ __forceinline__ void fma2(unsigned long long& c, unsigned long long a,
                                     unsigned long long b) {
    asm("fma.rn.f32x2 %0, %1, %2, %3;" : "=l"(c) : "l"(a), "l"(b), "l"(c));
}
__device__ __forceinline__ uint32_t umin32(uint32_t a, uint32_t b) { return a < b ? a : b; }

// D += A(16x32 s8, row) @ B(32x8 s8, col), s32 accum
__device__ __forceinline__ void mma_s8(int* d, uint32_t a0, uint32_t a1,
                                       uint32_t a2, uint32_t a3,
                                       uint32_t b0, uint32_t b1) {
    asm volatile(
        "mma.sync.aligned.m16n8k32.row.col.s32.s8.s8.s32 "
        "{%0,%1,%2,%3}, {%4,%5,%6,%7}, {%8,%9}, {%0,%1,%2,%3};"
        : "+r"(d[0]), "+r"(d[1]), "+r"(d[2]), "+r"(d[3])
        : "r"(a0), "r"(a1), "r"(a2), "r"(a3), "r"(b0), "r"(b1));
}

// fp32 micro-kernel for transform (8q x 4c per thread)
#define MICRO_KK(kk)                                                          \
    {                                                                         \
        float4 q0 = *reinterpret_cast<const float4*>(&As[(kk) * 64 + w8]);    \
        float4 q1 = *reinterpret_cast<const float4*>(&As[(kk) * 64 + w8 + 4]);\
        ulonglong2 b = *reinterpret_cast<const ulonglong2*>(&Bs[(kk) * 128 + lane4]); \
        unsigned long long a0 = pk2(q0.x, q0.x), a1 = pk2(q0.y, q0.y);        \
        unsigned long long a2 = pk2(q0.z, q0.z), a3 = pk2(q0.w, q0.w);        \
        unsigned long long a4 = pk2(q1.x, q1.x), a5 = pk2(q1.y, q1.y);        \
        unsigned long long a6 = pk2(q1.z, q1.z), a7 = pk2(q1.w, q1.w);        \
        fma2(acc[0][0], a0, b.x); fma2(acc[0][1], a0, b.y);                   \
        fma2(acc[1][0], a1, b.x); fma2(acc[1][1], a1, b.y);                   \
        fma2(acc[2][0], a2, b.x); fma2(acc[2][1], a2, b.y);                   \
        fma2(acc[3][0], a3, b.x); fma2(acc[3][1], a3, b.y);                   \
        fma2(acc[4][0], a4, b.x); fma2(acc[4][1], a4, b.y);                   \
        fma2(acc[5][0], a5, b.x); fma2(acc[5][1], a5, b.y);                   \
        fma2(acc[6][0], a6, b.x); fma2(acc[6][1], a6, b.y);                   \
        fma2(acc[7][0], a7, b.x); fma2(acc[7][1], a7, b.y);                   \
    }

// ================= kernel 1: h = tanh(X @ W + b)  (fp32, single-buffer R11) ======
__global__ void __launch_bounds__(256, 2) k_transform(const float* __restrict__ A,
                                                      const float* __restrict__ W,
                                                      const float* __restrict__ bias,
                                                      int M, int to_mem) {
    __shared__ __align__(16) float As[32 * 64];
    __shared__ __align__(16) float Bs[32 * 128];
    float* __restrict__ out = to_mem ? g_mh : g_qh;

    const int tid = threadIdx.x;
    const int w8 = (tid >> 5) * 8;
    const int lane4 = (tid & 31) * 4;
    const int rbase = blockIdx.x * 64;
    const int cbase = blockIdx.y * 128;

    unsigned long long acc[8][2];
#pragma unroll
    for (int i = 0; i < 8; i++) { acc[i][0] = 0ull; acc[i][1] = 0ull; }

    const int sr = tid & 63;
    const int skq = tid >> 6;
    const int wkw = tid >> 3;
    const int wcs = (tid & 7) * 16;

    for (int ko = 0; ko < D_; ko += 32) {
        {
            int gr = rbase + sr;
            float4 v0 = {0,0,0,0}, v1 = {0,0,0,0};
            if (gr < M) {
                const float4* p = reinterpret_cast<const float4*>(A + (size_t)gr * D_ + ko + skq * 8);
                v0 = p[0]; v1 = p[1];
            }
            float vv[8] = {v0.x,v0.y,v0.z,v0.w,v1.x,v1.y,v1.z,v1.w};
#pragma unroll
            for (int i = 0; i < 8; i++) As[(skq * 8 + i) * 64 + sr] = vv[i];
        }
        {
            const float4* p = reinterpret_cast<const float4*>(W + (size_t)(ko + wkw) * D_ + cbase + wcs);
            float4 w0 = p[0], w1 = p[1], w2 = p[2], w3 = p[3];
            float4* q = reinterpret_cast<float4*>(&Bs[wkw * 128 + wcs]);
            q[0] = w0; q[1] = w1; q[2] = w2; q[3] = w3;
        }
        __syncthreads();
#pragma unroll
        for (int kk = 0; kk < 32; kk++) MICRO_KK(kk)
        __syncthreads();
    }

    const int c0 = cbase + lane4;
    float4 b4 = *reinterpret_cast<const float4*>(bias + c0);
#pragma unroll
    for (int i = 0; i < 8; i++) {
        int r = rbase + w8 + i;
        if (r < M) {
            float2 v0 = up2(acc[i][0]), v1 = up2(acc[i][1]);
            float4 o;
            o.x = tanhf(v0.x + b4.x); o.y = tanhf(v0.y + b4.y);
            o.z = tanhf(v1.x + b4.z); o.w = tanhf(v1.y + b4.w);
            *reinterpret_cast<float4*>(out + (size_t)r * D_ + c0) = o;
        }
    }
}

// ==== kernel 2: Poincare rescale (in place) + sumsq + int8 pack ====
__global__ void __launch_bounds__(256) k_normalize(int which, int M) {
    float* __restrict__ h  = which ? g_mh  : g_qh;
    float* __restrict__ sq = which ? g_msq : g_qsq;
    uint32_t* __restrict__ hb = which ? g_mhb : g_qhb;
    int row = blockIdx.x * 8 + (threadIdx.x >> 5);
    if (row >= M) return;
    int lane = threadIdx.x & 31;
    size_t off = (size_t)row * D_ + lane * 8;
    float4* p = reinterpret_cast<float4*>(h + off);
    float4 v0 = p[0], v1 = p[1];
    float s = v0.x*v0.x + v0.y*v0.y + v0.z*v0.z + v0.w*v0.w
            + v1.x*v1.x + v1.y*v1.y + v1.z*v1.z + v1.w*v1.w;
#pragma unroll
    for (int o = 16; o; o >>= 1) s += __shfl_xor_sync(0xffffffffu, s, o);
    float norm = sqrtf(s);
    float scale = (norm > 0.95f) ? (0.95f / norm) : 1.0f;
    float y[8] = {v0.x*scale, v0.y*scale, v0.z*scale, v0.w*scale,
                  v1.x*scale, v1.y*scale, v1.z*scale, v1.w*scale};
    p[0] = make_float4(y[0], y[1], y[2], y[3]);
    p[1] = make_float4(y[4], y[5], y[6], y[7]);
    float s2 = 0.0f;
#pragma unroll
    for (int i = 0; i < 8; i++) s2 += y[i] * y[i];
#pragma unroll
    for (int o = 16; o; o >>= 1) s2 += __shfl_xor_sync(0xffffffffu, s2, o);
    if (lane == 0) sq[row] = s2;
    // int8 pack: |y| <= 0.95 -> q in [-127, 127]
    int qv[8];
#pragma unroll
    for (int i = 0; i < 8; i++) qv[i] = __float2int_rn(y[i] * Q_SCALE);
    uint32_t w0 = (qv[0] & 0xFF) | ((qv[1] & 0xFF) << 8) |
                  ((qv[2] & 0xFF) << 16) | ((uint32_t)(qv[3] & 0xFF) << 24);
    uint32_t w1 = (qv[4] & 0xFF) | ((qv[5] & 0xFF) << 8) |
                  ((qv[6] & 0xFF) << 16) | ((uint32_t)(qv[7] & 0xFF) << 24);
    *reinterpret_cast<uint2*>(hb + (size_t)row * 64 + lane * 2) = make_uint2(w0, w1);
}

// ==== kernel 3: int8 filter GEMM + fused top-3 candidates (single-buffer) ====
// block 64q x 128m; 8 warps = 4 qw x 2 nw; warp 16q x 64m; mma m16n8k32.s8.
// smem uint2 = (word w, word w+4) within a k32 block -> conflict-free LDS.64.
__global__ void __launch_bounds__(256) k_dist_cand() {
    __shared__ __align__(16) uint2 Ap[2 * 64 * 4];     // [kb][qrow][tig]  4 KB
    __shared__ __align__(16) uint2 Mp[2 * 128 * 4];    // [kb][mrow][tig]  8 KB

    const int tid = threadIdx.x;
    const int warp = tid >> 5, lane = tid & 31;
    const int g = lane >> 2, tig = lane & 3;
    const int qw = (warp & 3) * 16;
    const int nwbit = warp >> 2;
    const int nw = nwbit * 64;
    const int qbase = blockIdx.x * 64;
    const int mb = blockIdx.y * 128;

    int acc[8][4];
#pragma unroll
    for (int j = 0; j < 8; j++)
#pragma unroll
        for (int c = 0; c < 4; c++) acc[j][c] = 0;

    const int qr_ = tid & 63, qkb = (tid >> 6) & 1;   // Q staging (tid < 128)
    const int mr_ = tid & 127, mkb = tid >> 7;        // M staging (all threads)

    for (int ch = 0; ch < 4; ch++) {            // k chunks of 64 (2 k32 blocks)
        const int wb = ch * 16;                 // word base within row
        if (tid < 128) {                        // Q tile: 64 rows x 2 kb
            const uint4* p = reinterpret_cast<const uint4*>(
                g_qhb + (size_t)(qbase + qr_) * 64 + wb + qkb * 8);
            uint4 u0 = p[0], u1 = p[1];
            uint2* d = &Ap[(qkb * 64 + qr_) * 4];
            d[0] = make_uint2(u0.x, u1.x);
            d[1] = make_uint2(u0.y, u1.y);
            d[2] = make_uint2(u0.z, u1.z);
            d[3] = make_uint2(u0.w, u1.w);
        }
        {                                       // M tile: 128 rows x 2 kb
            int gm = mb + mr_;
            uint4 u0 = {0,0,0,0}, u1 = {0,0,0,0};
            if (gm < N_) {
                const uint4* p = reinterpret_cast<const uint4*>(
                    g_mhb + (size_t)gm * 64 + wb + mkb * 8);
                u0 = p[0]; u1 = p[1];
            }
            uint2* d = &Mp[(mkb * 128 + mr_) * 4];
            d[0] = make_uint2(u0.x, u1.x);
            d[1] = make_uint2(u0.y, u1.y);
            d[2] = make_uint2(u0.z, u1.z);
            d[3] = make_uint2(u0.w, u1.w);
        }
        __syncthreads();
#pragma unroll
        for (int kb = 0; kb < 2; kb++) {
            uint2 aA = Ap[(kb * 64 + qw + g) * 4 + tig];       // a0, a2
            uint2 aB = Ap[(kb * 64 + qw + g + 8) * 4 + tig];   // a1, a3
#pragma unroll
            for (int jn = 0; jn < 8; jn++) {
                uint2 bb = Mp[(kb * 128 + nw + jn * 8 + g) * 4 + tig];  // b0, b1
                mma_s8(acc[jn], aA.x, aB.x, aA.y, aB.y, bb.x, bb.y);
            }
        }
        __syncthreads();
    }

    // epilogue: approx arg + per-thread top-3 (32-bit keys), per q-row
    const int q0 = qbase + qw + g;
#pragma unroll
    for (int i = 0; i < 2; i++) {
        const int qr = q0 + i * 8;
        const float qs = g_qsq[qr];
        const float qa = 1.0f - qs;
        uint32_t t0 = 0xFFFFFFFFu, t1 = 0xFFFFFFFFu, t2 = 0xFFFFFFFFu;
#pragma unroll
        for (int jn = 0; jn < 8; jn++) {
#pragma unroll
            for (int h = 0; h < 2; h++) {
                int m = mb + nw + jn * 8 + 2 * tig + h;
                if (m < N_) {
                    float ms = g_msq[m];
                    float dot = (float)acc[jn][i * 2 + h] * DOT_SCALE;
                    float diff = fmaxf(qs + ms - 2.0f * dot, 0.0f);
                    float arg = 1.0f + (2.0f * diff) / (qa * (1.0f - ms) + 1e-8f);
                    uint32_t key = (__float_as_uint(arg) & 0xFFFF0000u) | (uint32_t)m;
                    if (key < t2) {
                        if (key < t1) {
                            t2 = t1;
                            if (key < t0) { t1 = t0; t0 = key; } else t1 = key;
                        } else t2 = key;
                    }
                }
            }
        }
        size_t base = ((size_t)qr * TILES + blockIdx.y) * 24 + (nwbit * 4 + tig) * 3;
        g_cand[base]     = t0;
        g_cand[base + 1] = t1;
        g_cand[base + 2] = t2;
    }
}

// ==== kernel 4: merge candidates -> approx top-32 -> exact re-rank -> out ====
__global__ void __launch_bounds__(256) k_merge(const float* __restrict__ masks,
                                               float* __restrict__ out) {
    const int q = blockIdx.x, tid = threadIdx.x;
    const int wid = tid >> 5, lane = tid & 31;
    const uint32_t* __restrict__ cand = g_cand + (size_t)q * (TILES * 24);
    const int TOT = TILES * 24;

    // per-thread top-8 of ~37 keys
    uint32_t best[8];
#pragma unroll
    for (int s = 0; s < 8; s++) best[s] = 0xFFFFFFFFu;
    for (int i = tid; i < TOT; i += 256) {
        uint32_t k = cand[i];
        if (k < best[7]) {
            best[7] = k;
#pragma unroll
            for (int s = 7; s > 0; s--) {
                if (best[s] < best[s - 1]) {
                    uint32_t t = best[s]; best[s] = best[s - 1]; best[s - 1] = t;
                }
            }
        }
    }

    __shared__ uint32_t red[8];
    __shared__ uint32_t wks;
    __shared__ int cidx[CAND];
    __shared__ unsigned long long ekeys[CAND];
    __shared__ int fidx[K_];

    // extract block-wide CAND smallest approx keys
    for (int s = 0; s < CAND; s++) {
        uint32_t lm = best[0];
#pragma unroll
        for (int o = 16; o; o >>= 1)
            lm = umin32(lm, __shfl_xor_sync(0xffffffffu, lm, o));
        if (lane == 0) red[wid] = lm;
        __syncthreads();
        if (tid == 0) {
            uint32_t m = red[0];
#pragma unroll
            for (int i = 1; i < 8; i++) m = umin32(m, red[i]);
            wks = m;
            cidx[s] = (int)(m & 0xFFFFu);
        }
        __syncthreads();
        if (best[0] == wks) {       // keys unique (idx embedded)
#pragma unroll
            for (int i = 0; i < 7; i++) best[i] = best[i + 1];
            best[7] = 0xFFFFFFFFu;
        }
        __syncthreads();
    }

    // exact fp32 re-rank of 32 candidates (one per warp, 4 rounds)
    const float4* qp = reinterpret_cast<const float4*>(g_qh + (size_t)q * D_ + lane * 8);
    float4 a0 = qp[0], a1 = qp[1];
    const float qs = g_qsq[q];
    const float qa = 1.0f - qs;
#pragma unroll
    for (int r = 0; r < 4; r++) {
        int c = wid + 8 * r;
        int idx = cidx[c];
        const float4* mp = reinterpret_cast<const float4*>(g_mh + (size_t)idx * D_ + lane * 8);
        float4 b0 = mp[0], b1 = mp[1];
        float dot = a0.x*b0.x + a0.y*b0.y + a0.z*b0.z + a0.w*b0.w
                  + a1.x*b1.x + a1.y*b1.y + a1.z*b1.z + a1.w*b1.w;
#pragma unroll
        for (int o = 16; o; o >>= 1) dot += __shfl_xor_sync(0xffffffffu, dot, o);
        if (lane == 0) {
            float ms = g_msq[idx];
            float diff = fmaxf(qs + ms - 2.0f * dot, 0.0f);
            float arg = 1.0f + (2.0f * diff) / (qa * (1.0f - ms) + 1e-8f);
            ekeys[c] = ((unsigned long long)__float_as_uint(arg) << 32) | (unsigned)idx;
        }
    }
    __syncthreads();

    // exact top-8 of 32, softmax
    if (tid == 0) {
        unsigned long long k[CAND];
#pragma unroll
        for (int i = 0; i < CAND; i++) k[i] = ekeys[i];
        for (int i = 1; i < CAND; i++) {
            unsigned long long x = k[i];
            int j = i - 1;
            while (j >= 0 && k[j] > x) { k[j + 1] = k[j]; j--; }
            k[j + 1] = x;
        }
        float d[K_], w[K_], sum = 0.0f;
#pragma unroll
        for (int s = 0; s < K_; s++) {
            float arg = __uint_as_float((unsigned)(k[s] >> 32));
            d[s] = acoshf(fmaxf(arg, 1.0f + 1e-6f));
            fidx[s] = (int)(unsigned)(k[s] & 0xffffffffu);
        }
#pragma unroll
        for (int s = 0; s < K_; s++) { w[s] = expf(d[0] - d[s]); sum += w[s]; }
#pragma unroll
        for (int s = 0; s < K_; s++)
            out[(size_t)q * K_ + s] = w[s] / sum;
    }
    __syncthreads();

    // gather som_hints
    float* __restrict__ hints = out + (size_t)B_ * K_;
    for (int s = 0; s < K_; s++) {
        const float* __restrict__ src = masks + (size_t)fidx[s] * MA_;
        float* __restrict__ dst = hints + ((size_t)q * K_ + s) * MA_;
        for (int t = tid; t < MA_; t += 256) dst[t] = src[t];
    }
}

extern "C" void kernel_launch(void* const* d_in, const int* in_sizes, int n_in,
                              void* d_out, int out_size) {
    const float* q_emb  = (const float*)d_in[0];
    const float* m_emb  = (const float*)d_in[1];
    const float* masks  = (const float*)d_in[2];
    const float* W      = (const float*)d_in[3];
    const float* b      = (const float*)d_in[4];
    float* out = (float*)d_out;

    k_transform<<<dim3(B_ / 64, 2), 256>>>(q_emb, W, b, B_, 0);
    k_transform<<<dim3((N_ + 63) / 64, 2), 256>>>(m_emb, W, b, N_, 1);
    k_normalize<<<(B_ + 7) / 8, 256>>>(0, B_);
    k_normalize<<<(N_ + 7) / 8, 256>>>(1, N_);
    k_dist_cand<<<dim3(B_ / 64, TILES), 256>>>();
    k_merge<<<B_, 256>>>(masks, out);
}

// round 16
// speedup vs baseline: 1.1827x; 1.0004x over previous
#include <cuda_runtime.h>
#include <cuda_bf16.h>
#include <cfloat>
#include <math.h>
#include <stdint.h>

#define B_   1024
#define N_   50000
#define D_   256
#define MA_  200
#define K_   8
#define CAND 32
#define TILES 391              // ceil(50000/128)

// ---------- device scratch ----------
__device__ float g_qh[B_ * D_];                    // exact fp32 (rescaled)
__device__ float g_mh[(size_t)N_ * D_];
__device__ uint32_t g_qhb[B_ * 64];                // int8 packed words (4 s8/word)
__device__ uint32_t g_mhb[(size_t)N_ * 64];
__device__ float g_qsq[B_];
__device__ float g_msq[N_];
__device__ float g_minv[N_];                       // 1/(1 - msq)
__device__ uint32_t g_wt[3][256 * 128];            // W^T bf16x3 splits, packed pairs
__device__ uint32_t g_cand[(size_t)B_ * TILES * 24];   // 38.4 MB

#define Q_SCALE   133.684210f          // 127 / 0.95
#define DOT_SCALE 5.59450274e-5f       // (0.95/127)^2

// ---------- helpers ----------
__device__ __forceinline__ uint32_t umin32(uint32_t a, uint32_t b) { return a < b ? a : b; }

// D += A(16x16 bf16, row) @ B(16x8 bf16, col), fp32 accum
__device__ __forceinline__ void mma_bf16(float* d, uint32_t a0, uint32_t a1,
                                         uint32_t a2, uint32_t a3,
                                         uint32_t b0, uint32_t b1) {
    asm volatile(
        "mma.sync.aligned.m16n8k16.row.col.f32.bf16.bf16.f32 "
        "{%0,%1,%2,%3}, {%4,%5,%6,%7}, {%8,%9}, {%0,%1,%2,%3};"
        : "+f"(d[0]), "+f"(d[1]), "+f"(d[2]), "+f"(d[3])
        : "r"(a0), "r"(a1), "r"(a2), "r"(a3), "r"(b0), "r"(b1));
}

// D += A(16x32 s8, row) @ B(32x8 s8, col), s32 accum
__device__ __forceinline__ void mma_s8(int* d, uint32_t a0, uint32_t a1,
                                       uint32_t a2, uint32_t a3,
                                       uint32_t b0, uint32_t b1) {
    asm volatile(
        "mma.sync.aligned.m16n8k32.row.col.s32.s8.s8.s32 "
        "{%0,%1,%2,%3}, {%4,%5,%6,%7}, {%8,%9}, {%0,%1,%2,%3};"
        : "+r"(d[0]), "+r"(d[1]), "+r"(d[2]), "+r"(d[3])
        : "r"(a0), "r"(a1), "r"(a2), "r"(a3), "r"(b0), "r"(b1));
}

// bf16 3-level split: x = b0 + b1 + b2 + O(2^-27 x). Splits are exact subtractions.
__device__ __forceinline__ void bsplit3(float x, uint32_t& o0, uint32_t& o1, uint32_t& o2) {
    __nv_bfloat16 h0 = __float2bfloat16(x);
    float r = x - __bfloat162float(h0);
    __nv_bfloat16 h1 = __float2bfloat16(r);
    r -= __bfloat162float(h1);
    __nv_bfloat16 h2 = __float2bfloat16(r);
    o0 = (uint32_t)__bfloat16_as_ushort(h0);
    o1 = (uint32_t)__bfloat16_as_ushort(h1);
    o2 = (uint32_t)__bfloat16_as_ushort(h2);
}

// ==== kernel 0: W^T split into 3 bf16 levels, packed k-pairs ====
// g_wt[l][c*128 + w] = (bf16_l(W[2w][c]), bf16_l(W[2w+1][c])) packed lo|hi
__global__ void __launch_bounds__(128) k_prep_w(const float* __restrict__ W) {
    const int c = blockIdx.x;          // 0..255
    const int w = threadIdx.x;         // 0..127
    float x0 = W[(size_t)(2 * w) * D_ + c];
    float x1 = W[(size_t)(2 * w + 1) * D_ + c];
    uint32_t a0, a1, a2, b0, b1, b2;
    bsplit3(x0, a0, a1, a2);
    bsplit3(x1, b0, b1, b2);
    const int o = c * 128 + w;
    g_wt[0][o] = a0 | (b0 << 16);
    g_wt[1][o] = a1 | (b1 << 16);
    g_wt[2][o] = a2 | (b2 << 16);
}

// ==== kernel 1: h = tanh(X @ W + b) via bf16x6 tensor-core GEMM ====
// block 64 rows x 128 cols; 8 warps = 4 row-groups x 2 col-groups; warp 16x64.
// smem uint2 = (word w, word w+4) within each k16 block -> conflict-free LDS.64.
__global__ void __launch_bounds__(256) k_transform_tc(const float* __restrict__ A,
                                                      const float* __restrict__ bias,
                                                      int M, int to_mem) {
    __shared__ __align__(16) uint2 Ap[3][2 * 64 * 4];     // 12 KB
    __shared__ __align__(16) uint2 Wp[3][2 * 128 * 4];    // 24 KB
    float* __restrict__ out = to_mem ? g_mh : g_qh;

    const int tid = threadIdx.x;
    const int warp = tid >> 5, lane = tid & 31;
    const int g = lane >> 2, tig = lane & 3;
    const int qw = (warp & 3) * 16;
    const int nw = (warp >> 2) * 64;
    const int rbase = blockIdx.x * 64;
    const int cbase = blockIdx.y * 128;

    float acc[8][4];
#pragma unroll
    for (int j = 0; j < 8; j++)
#pragma unroll
        for (int c = 0; c < 4; c++) acc[j][c] = 0.0f;

    const int ar = tid & 63, akb = (tid >> 6) & 1;   // A staging (tid < 128)
    const int wc = tid & 127, wkb = tid >> 7;        // W staging (all threads)

    for (int ch = 0; ch < 8; ch++) {                 // k chunks of 32
        if (tid < 128) {                             // A: 64 rows x 32 k (fp32 -> split)
            int gr = rbase + ar;
            float xv[16];
            if (gr < M) {
                const float4* p = reinterpret_cast<const float4*>(
                    A + (size_t)gr * D_ + ch * 32 + akb * 16);
                float4 v0 = p[0], v1 = p[1], v2 = p[2], v3 = p[3];
                xv[0]=v0.x; xv[1]=v0.y; xv[2]=v0.z; xv[3]=v0.w;
                xv[4]=v1.x; xv[5]=v1.y; xv[6]=v1.z; xv[7]=v1.w;
                xv[8]=v2.x; xv[9]=v2.y; xv[10]=v2.z; xv[11]=v2.w;
                xv[12]=v3.x; xv[13]=v3.y; xv[14]=v3.z; xv[15]=v3.w;
            } else {
#pragma unroll
                for (int i = 0; i < 16; i++) xv[i] = 0.0f;
            }
            uint32_t wd0[8], wd1[8], wd2[8];
#pragma unroll
            for (int t = 0; t < 8; t++) {
                uint32_t a0, a1, a2, b0, b1, b2;
                bsplit3(xv[2 * t], a0, a1, a2);
                bsplit3(xv[2 * t + 1], b0, b1, b2);
                wd0[t] = a0 | (b0 << 16);
                wd1[t] = a1 | (b1 << 16);
                wd2[t] = a2 | (b2 << 16);
            }
            const int abase = (akb * 64 + ar) * 4;
#pragma unroll
            for (int t = 0; t < 4; t++) {
                Ap[0][abase + t] = make_uint2(wd0[t], wd0[t + 4]);
                Ap[1][abase + t] = make_uint2(wd1[t], wd1[t + 4]);
                Ap[2][abase + t] = make_uint2(wd2[t], wd2[t + 4]);
            }
        }
        {                                            // W^T: 128 c-rows x 16 words
            const int base = (cbase + wc) * 128 + ch * 16 + wkb * 8;
            const int dbase = (wkb * 128 + wc) * 4;
#pragma unroll
            for (int l = 0; l < 3; l++) {
                uint4 u0 = *reinterpret_cast<const uint4*>(&g_wt[l][base]);
                uint4 u1 = *reinterpret_cast<const uint4*>(&g_wt[l][base + 4]);
                Wp[l][dbase + 0] = make_uint2(u0.x, u1.x);
                Wp[l][dbase + 1] = make_uint2(u0.y, u1.y);
                Wp[l][dbase + 2] = make_uint2(u0.z, u1.z);
                Wp[l][dbase + 3] = make_uint2(u0.w, u1.w);
            }
        }
        __syncthreads();
#pragma unroll
        for (int kb = 0; kb < 2; kb++) {
            const int arow = (kb * 64 + qw + g) * 4 + tig;
            const int brow = arow + 32;              // +8 rows * 4
            uint2 aA0 = Ap[0][arow], aB0 = Ap[0][brow];
            uint2 aA1 = Ap[1][arow], aB1 = Ap[1][brow];
            uint2 aA2 = Ap[2][arow], aB2 = Ap[2][brow];
#pragma unroll
            for (int jn = 0; jn < 8; jn++) {
                const int mi = (kb * 128 + nw + jn * 8 + g) * 4 + tig;
                uint2 b0 = Wp[0][mi], b1 = Wp[1][mi], b2 = Wp[2][mi];
                mma_bf16(acc[jn], aA2.x, aB2.x, aA2.y, aB2.y, b0.x, b0.y);  // x2*w0
                mma_bf16(acc[jn], aA0.x, aB0.x, aA0.y, aB0.y, b2.x, b2.y);  // x0*w2
                mma_bf16(acc[jn], aA1.x, aB1.x, aA1.y, aB1.y, b1.x, b1.y);  // x1*w1
                mma_bf16(acc[jn], aA1.x, aB1.x, aA1.y, aB1.y, b0.x, b0.y);  // x1*w0
                mma_bf16(acc[jn], aA0.x, aB0.x, aA0.y, aB0.y, b1.x, b1.y);  // x0*w1
                mma_bf16(acc[jn], aA0.x, aB0.x, aA0.y, aB0.y, b0.x, b0.y);  // x0*w0
            }
        }
        __syncthreads();
    }

    // epilogue: + bias, tanh, store (thread covers rows r0,r1 x 16 cols)
    const int r0 = rbase + qw + g, r1 = r0 + 8;
#pragma unroll
    for (int jn = 0; jn < 8; jn++) {
        const int c = cbase + nw + jn * 8 + 2 * tig;
        float2 bv = *reinterpret_cast<const float2*>(bias + c);
        if (r0 < M)
            *reinterpret_cast<float2*>(out + (size_t)r0 * D_ + c) =
                make_float2(tanhf(acc[jn][0] + bv.x), tanhf(acc[jn][1] + bv.y));
        if (r1 < M)
            *reinterpret_cast<float2*>(out + (size_t)r1 * D_ + c) =
                make_float2(tanhf(acc[jn][2] + bv.x), tanhf(acc[jn][3] + bv.y));
    }
}

// ==== kernel 2: Poincare rescale (in place) + sumsq + int8 pack + minv ====
__global__ void __launch_bounds__(256) k_normalize(int which, int M) {
    float* __restrict__ h  = which ? g_mh  : g_qh;
    float* __restrict__ sq = which ? g_msq : g_qsq;
    uint32_t* __restrict__ hb = which ? g_mhb : g_qhb;
    int row = blockIdx.x * 8 + (threadIdx.x >> 5);
    if (row >= M) return;
    int lane = threadIdx.x & 31;
    size_t off = (size_t)row * D_ + lane * 8;
    float4* p = reinterpret_cast<float4*>(h + off);
    float4 v0 = p[0], v1 = p[1];
    float s = v0.x*v0.x + v0.y*v0.y + v0.z*v0.z + v0.w*v0.w
            + v1.x*v1.x + v1.y*v1.y + v1.z*v1.z + v1.w*v1.w;
#pragma unroll
    for (int o = 16; o; o >>= 1) s += __shfl_xor_sync(0xffffffffu, s, o);
    float norm = sqrtf(s);
    float scale = (norm > 0.95f) ? (0.95f / norm) : 1.0f;
    float y[8] = {v0.x*scale, v0.y*scale, v0.z*scale, v0.w*scale,
                  v1.x*scale, v1.y*scale, v1.z*scale, v1.w*scale};
    p[0] = make_float4(y[0], y[1], y[2], y[3]);
    p[1] = make_float4(y[4], y[5], y[6], y[7]);
    float s2 = 0.0f;
#pragma unroll
    for (int i = 0; i < 8; i++) s2 += y[i] * y[i];
#pragma unroll
    for (int o = 16; o; o >>= 1) s2 += __shfl_xor_sync(0xffffffffu, s2, o);
    if (lane == 0) {
        sq[row] = s2;
        if (which) g_minv[row] = 1.0f / (1.0f - s2);   // s2 <= 0.9025
    }
    // int8 pack: |y| <= 0.95 -> q in [-127, 127]
    int qv[8];
#pragma unroll
    for (int i = 0; i < 8; i++) qv[i] = __float2int_rn(y[i] * Q_SCALE);
    uint32_t w0 = (qv[0] & 0xFF) | ((qv[1] & 0xFF) << 8) |
                  ((qv[2] & 0xFF) << 16) | ((uint32_t)(qv[3] & 0xFF) << 24);
    uint32_t w1 = (qv[4] & 0xFF) | ((qv[5] & 0xFF) << 8) |
                  ((qv[6] & 0xFF) << 16) | ((uint32_t)(qv[7] & 0xFF) << 24);
    *reinterpret_cast<uint2*>(hb + (size_t)row * 64 + lane * 2) = make_uint2(w0, w1);
}

// ==== kernel 3: int8 filter GEMM + fused top-3 candidates (division-free) ====
__global__ void __launch_bounds__(256) k_dist_cand() {
    __shared__ __align__(16) uint2 Ap[2 * 64 * 4];     // 4 KB
    __shared__ __align__(16) uint2 Mp[2 * 128 * 4];    // 8 KB

    const int tid = threadIdx.x;
    const int warp = tid >> 5, lane = tid & 31;
    const int g = lane >> 2, tig = lane & 3;
    const int qw = (warp & 3) * 16;
    const int nwbit = warp >> 2;
    const int nw = nwbit * 64;
    const int qbase = blockIdx.x * 64;
    const int mb = blockIdx.y * 128;

    int acc[8][4];
#pragma unroll
    for (int j = 0; j < 8; j++)
#pragma unroll
        for (int c = 0; c < 4; c++) acc[j][c] = 0;

    const int qr_ = tid & 63, qkb = (tid >> 6) & 1;
    const int mr_ = tid & 127, mkb = tid >> 7;

    for (int ch = 0; ch < 4; ch++) {
        const int wb = ch * 16;
        if (tid < 128) {
            const uint4* p = reinterpret_cast<const uint4*>(
                g_qhb + (size_t)(qbase + qr_) * 64 + wb + qkb * 8);
            uint4 u0 = p[0], u1 = p[1];
            uint2* d = &Ap[(qkb * 64 + qr_) * 4];
            d[0] = make_uint2(u0.x, u1.x);
            d[1] = make_uint2(u0.y, u1.y);
            d[2] = make_uint2(u0.z, u1.z);
            d[3] = make_uint2(u0.w, u1.w);
        }
        {
            int gm = mb + mr_;
            uint4 u0 = {0,0,0,0}, u1 = {0,0,0,0};
            if (gm < N_) {
                const uint4* p = reinterpret_cast<const uint4*>(
                    g_mhb + (size_t)gm * 64 + wb + mkb * 8);
                u0 = p[0]; u1 = p[1];
            }
            uint2* d = &Mp[(mkb * 128 + mr_) * 4];
            d[0] = make_uint2(u0.x, u1.x);
            d[1] = make_uint2(u0.y, u1.y);
            d[2] = make_uint2(u0.z, u1.z);
            d[3] = make_uint2(u0.w, u1.w);
        }
        __syncthreads();
#pragma unroll
        for (int kb = 0; kb < 2; kb++) {
            uint2 aA = Ap[(kb * 64 + qw + g) * 4 + tig];
            uint2 aB = Ap[(kb * 64 + qw + g + 8) * 4 + tig];
#pragma unroll
            for (int jn = 0; jn < 8; jn++) {
                uint2 bb = Mp[(kb * 128 + nw + jn * 8 + g) * 4 + tig];
                mma_s8(acc[jn], aA.x, aB.x, aA.y, aB.y, bb.x, bb.y);
            }
        }
        __syncthreads();
    }

    // epilogue: division-free monotone key s = diff * minv (per q-row ranking)
    const int q0 = qbase + qw + g;
#pragma unroll
    for (int i = 0; i < 2; i++) {
        const int qr = q0 + i * 8;
        const float qs = g_qsq[qr];
        uint32_t t0 = 0xFFFFFFFFu, t1 = 0xFFFFFFFFu, t2 = 0xFFFFFFFFu;
#pragma unroll
        for (int jn = 0; jn < 8; jn++) {
            int m0 = mb + nw + jn * 8 + 2 * tig;
            if (m0 < N_) {     // m0 even, N_ even -> m0+1 also valid
                float2 ms2 = *reinterpret_cast<const float2*>(g_msq + m0);
                float2 mi2 = *reinterpret_cast<const float2*>(g_minv + m0);
                {
                    float dot = (float)acc[jn][i * 2] * DOT_SCALE;
                    float diff = fmaxf(qs + ms2.x - 2.0f * dot, 0.0f);
                    float sv = diff * mi2.x;
                    uint32_t key = (__float_as_uint(sv) & 0xFFFF0000u) | (uint32_t)m0;
                    if (key < t2) {
                        if (key < t1) {
                            t2 = t1;
                            if (key < t0) { t1 = t0; t0 = key; } else t1 = key;
                        } else t2 = key;
                    }
                }
                {
                    float dot = (float)acc[jn][i * 2 + 1] * DOT_SCALE;
                    float diff = fmaxf(qs + ms2.y - 2.0f * dot, 0.0f);
                    float sv = diff * mi2.y;
                    uint32_t key = (__float_as_uint(sv) & 0xFFFF0000u) | (uint32_t)(m0 + 1);
                    if (key < t2) {
                        if (key < t1) {
                            t2 = t1;
                            if (key < t0) { t1 = t0; t0 = key; } else t1 = key;
                        } else t2 = key;
                    }
                }
            }
        }
        size_t base = ((size_t)qr * TILES + blockIdx.y) * 24 + (nwbit * 4 + tig) * 3;
        g_cand[base]     = t0;
        g_cand[base + 1] = t1;
        g_cand[base + 2] = t2;
    }
}

// ==== kernel 4: merge candidates -> approx top-32 -> exact re-rank -> out ====
__global__ void __launch_bounds__(256) k_merge(const float* __restrict__ masks,
                                               float* __restrict__ out) {
    const int q = blockIdx.x, tid = threadIdx.x;
    const int wid = tid >> 5, lane = tid & 31;
    const uint32_t* __restrict__ cand = g_cand + (size_t)q * (TILES * 24);
    const int TOT = TILES * 24;

    uint32_t best[8];
#pragma unroll
    for (int s = 0; s < 8; s++) best[s] = 0xFFFFFFFFu;
    for (int i = tid; i < TOT; i += 256) {
        uint32_t k = cand[i];
        if (k < best[7]) {
            best[7] = k;
#pragma unroll
            for (int s = 7; s > 0; s--) {
                if (best[s] < best[s - 1]) {
                    uint32_t t = best[s]; best[s] = best[s - 1]; best[s - 1] = t;
                }
            }
        }
    }

    __shared__ uint32_t red[8];
    __shared__ uint32_t wks;
    __shared__ int cidx[CAND];
    __shared__ unsigned long long ekeys[CAND];
    __shared__ int fidx[K_];

    for (int s = 0; s < CAND; s++) {
        uint32_t lm = best[0];
#pragma unroll
        for (int o = 16; o; o >>= 1)
            lm = umin32(lm, __shfl_xor_sync(0xffffffffu, lm, o));
        if (lane == 0) red[wid] = lm;
        __syncthreads();
        if (tid == 0) {
            uint32_t m = red[0];
#pragma unroll
            for (int i = 1; i < 8; i++) m = umin32(m, red[i]);
            wks = m;
            cidx[s] = (int)(m & 0xFFFFu);
        }
        __syncthreads();
        if (best[0] == wks) {
#pragma unroll
            for (int i = 0; i < 7; i++) best[i] = best[i + 1];
            best[7] = 0xFFFFFFFFu;
        }
        __syncthreads();
    }

    // exact fp32 re-rank of 32 candidates (one per warp, 4 rounds)
    const float4* qp = reinterpret_cast<const float4*>(g_qh + (size_t)q * D_ + lane * 8);
    float4 a0 = qp[0], a1 = qp[1];
    const float qs = g_qsq[q];
    const float qa = 1.0f - qs;
#pragma unroll
    for (int r = 0; r < 4; r++) {
        int c = wid + 8 * r;
        int idx = cidx[c];
        const float4* mp = reinterpret_cast<const float4*>(g_mh + (size_t)idx * D_ + lane * 8);
        float4 b0 = mp[0], b1 = mp[1];
        float dot = a0.x*b0.x + a0.y*b0.y + a0.z*b0.z + a0.w*b0.w
                  + a1.x*b1.x + a1.y*b1.y + a1.z*b1.z + a1.w*b1.w;
#pragma unroll
        for (int o = 16; o; o >>= 1) dot += __shfl_xor_sync(0xffffffffu, dot, o);
        if (lane == 0) {
            float ms = g_msq[idx];
            float diff = fmaxf(qs + ms - 2.0f * dot, 0.0f);
            float arg = 1.0f + (2.0f * diff) / (qa * (1.0f - ms) + 1e-8f);
            ekeys[c] = ((unsigned long long)__float_as_uint(arg) << 32) | (unsigned)idx;
        }
    }
    __syncthreads();

    if (tid == 0) {
        unsigned long long k[CAND];
#pragma unroll
        for (int i = 0; i < CAND; i++) k[i] = ekeys[i];
        for (int i = 1; i < CAND; i++) {
            unsigned long long x = k[i];
            int j = i - 1;
            while (j >= 0 && k[j] > x) { k[j + 1] = k[j]; j--; }
            k[j + 1] = x;
        }
        float d[K_], w[K_], sum = 0.0f;
#pragma unroll
        for (int s = 0; s < K_; s++) {
            float arg = __uint_as_float((unsigned)(k[s] >> 32));
            d[s] = acoshf(fmaxf(arg, 1.0f + 1e-6f));
            fidx[s] = (int)(unsigned)(k[s] & 0xffffffffu);
        }
#pragma unroll
        for (int s = 0; s < K_; s++) { w[s] = expf(d[0] - d[s]); sum += w[s]; }
#pragma unroll
        for (int s = 0; s < K_; s++)
            out[(size_t)q * K_ + s] = w[s] / sum;
    }
    __syncthreads();

    float* __restrict__ hints = out + (size_t)B_ * K_;
    for (int s = 0; s < K_; s++) {
        const float* __restrict__ src = masks + (size_t)fidx[s] * MA_;
        float* __restrict__ dst = hints + ((size_t)q * K_ + s) * MA_;
        for (int t = tid; t < MA_; t += 256) dst[t] = src[t];
    }
}

extern "C" void kernel_launch(void* const* d_in, const int* in_sizes, int n_in,
                              void* d_out, int out_size) {
    const float* q_emb  = (const float*)d_in[0];
    const float* m_emb  = (const float*)d_in[1];
    const float* masks  = (const float*)d_in[2];
    const float* W      = (const float*)d_in[3];
    const float* b      = (const float*)d_in[4];
    float* out = (float*)d_out;

    k_prep_w<<<256, 128>>>(W);
    k_transform_tc<<<dim3(B_ / 64, 2), 256>>>(q_emb, b, B_, 0);
    k_transform_tc<<<dim3((N_ + 63) / 64, 2), 256>>>(m_emb, b, N_, 1);
    k_normalize<<<(B_ + 7) / 8, 256>>>(0, B_);
    k_normalize<<<(N_ + 7) / 8, 256>>>(1, N_);
    k_dist_cand<<<dim3(B_ / 64, TILES), 256>>>();
    k_merge<<<B_, 256>>>(masks, out);
}